// round 9
// baseline (speedup 1.0000x reference)
#include <cuda_runtime.h>
#include <stdint.h>

#define BATCH   32
#define NBOX    8400
#define NCLS    80
#define NC      (NBOX*NCLS)       // 672000
#define TOPK    1024
#define CAP     2048
#define CAP1    8192
#define MAXDET  300
#define SCORE_T 0.001f
#define IOU_T   0.7f
#define T0      0.995f
#define V4_PER_BATCH (NC/4)             // 168000
#define TOTAL_V4 (BATCH*V4_PER_BATCH)   // 5376000
#define SCAN_BLOCKS (TOTAL_V4/2048)     // 2625 (256 thr * 8 unroll)

// ---- dynamic smem layout (bytes) for k_fused -------------------------------
#define SM_KEYS   0                       // 2048 * 8  = 16384
#define SM_HIST   16384                   // 4096 * 4  = 16384
#define SM_CHUNK  32768                   // 1024 * 4  = 4096
#define SM_Y1     36864                   // 1024 * 4
#define SM_X1     40960
#define SM_Y2     45056
#define SM_X2     49152
#define SM_AREA   53248
#define SM_MASK   57344                   // 1024*32*4 = 131072
#define SM_RANY   188416                  // 32 * 4
#define SM_TOTAL  188544

// ---------------- device scratch (static) -----------------------------------
__device__ int                g_c1[BATCH];            // reset by k_fused each run
__device__ unsigned long long g_cand1[BATCH][CAP1];

// ---------------- K1: single bandwidth pass, collect s > T0 -----------------
__global__ void __launch_bounds__(256) k_scan(const float* __restrict__ scores) {
    int tid  = threadIdx.x;
    int lane = tid & 31;
    size_t blockBase = (size_t)blockIdx.x * 2048;   // float4 units
    const float4* __restrict__ p = (const float4*)scores;

    float4 v[8];
#pragma unroll
    for (int k = 0; k < 8; k++)
        v[k] = p[blockBase + (size_t)k * 256 + tid];

    int b0 = (int)(blockBase / V4_PER_BATCH);
    int bL = (int)((blockBase + 2047) / V4_PER_BATCH);
    bool uniformB = (b0 == bL);

    int cnt = 0;
#pragma unroll
    for (int k = 0; k < 8; k++) {
        float a[4] = {v[k].x, v[k].y, v[k].z, v[k].w};
#pragma unroll
        for (int c = 0; c < 4; c++) cnt += (a[c] > T0) ? 1 : 0;
    }

    if (uniformB) {
        int incl = cnt;
#pragma unroll
        for (int o = 1; o < 32; o <<= 1) {
            int n = __shfl_up_sync(0xffffffffu, incl, o);
            if (lane >= o) incl += n;
        }
        int excl  = incl - cnt;
        int total = __shfl_sync(0xffffffffu, incl, 31);
        int base  = 0;
        if (total > 0) {
            if (lane == 0) base = atomicAdd(&g_c1[b0], total);
            base = __shfl_sync(0xffffffffu, base, 0);
        }
        if (cnt > 0) {
            int w = base + excl;
            size_t batchBase4 = (size_t)b0 * V4_PER_BATCH;
#pragma unroll
            for (int k = 0; k < 8; k++) {
                float a[4] = {v[k].x, v[k].y, v[k].z, v[k].w};
                size_t idx4 = blockBase + (size_t)k * 256 + tid;
#pragma unroll
                for (int c = 0; c < 4; c++) {
                    if (a[c] > T0) {
                        unsigned flat = (unsigned)((idx4 - batchBase4) * 4 + c);
                        unsigned sb = __float_as_uint(a[c]);
                        if (w < CAP1)
                            g_cand1[b0][w] = ((unsigned long long)sb << 32) |
                                             (unsigned long long)(0xFFFFFFFFu - flat);
                        w++;
                    }
                }
            }
        }
    } else {
#pragma unroll
        for (int k = 0; k < 8; k++) {
            float a[4] = {v[k].x, v[k].y, v[k].z, v[k].w};
            size_t idx4 = blockBase + (size_t)k * 256 + tid;
            int be = (int)(idx4 / V4_PER_BATCH);
#pragma unroll
            for (int c = 0; c < 4; c++) {
                if (a[c] > T0) {
                    unsigned flat = (unsigned)((idx4 - (size_t)be * V4_PER_BATCH) * 4 + c);
                    unsigned sb = __float_as_uint(a[c]);
                    int pos = atomicAdd(&g_c1[be], 1);
                    if (pos < CAP1)
                        g_cand1[be][pos] = ((unsigned long long)sb << 32) |
                                           (unsigned long long)(0xFFFFFFFFu - flat);
                }
            }
        }
    }
}

// ---------------- hybrid bitonic helpers ------------------------------------
__device__ __forceinline__ unsigned long long shfl_xor64(unsigned long long v, int lx) {
    return __shfl_xor_sync(0xffffffffu, v, lx);
}

__device__ __forceinline__ void reg_phase(unsigned long long& v0, unsigned long long& v1,
                                          int t, int k, int jstart) {
    bool desc = ((t & (k >> 1)) == 0);
    for (int j = jstart; j >= 2; j >>= 1) {
        int lx = j >> 1;
        bool low = ((t & lx) == 0);
        bool takeMax = (low == desc);
        unsigned long long o0 = shfl_xor64(v0, lx);
        unsigned long long o1 = shfl_xor64(v1, lx);
        v0 = takeMax ? (v0 > o0 ? v0 : o0) : (v0 < o0 ? v0 : o0);
        v1 = takeMax ? (v1 > o1 ? v1 : o1) : (v1 < o1 ? v1 : o1);
    }
    if (desc ? (v0 < v1) : (v0 > v1)) {
        unsigned long long tmp = v0; v0 = v1; v1 = tmp;
    }
}

__device__ __forceinline__ int fine_bucket(float s) {
    int bk = (int)((s - 0.9f) * 40960.0f);
    if (bk < 0) bk = 0; if (bk > 4095) bk = 4095;
    return bk;
}

// ---------------- K2: fused select + mask + NMS + output --------------------
__global__ void __launch_bounds__(1024) k_fused(const float* __restrict__ boxes,
                                                const float* __restrict__ scores,
                                                float* __restrict__ out) {
    extern __shared__ char dyn[];
    unsigned long long* smKeys = (unsigned long long*)(dyn + SM_KEYS);
    unsigned int* hist  = (unsigned int*)(dyn + SM_HIST);
    unsigned int* chunk = (unsigned int*)(dyn + SM_CHUNK);
    float* sy1 = (float*)(dyn + SM_Y1);
    float* sx1 = (float*)(dyn + SM_X1);
    float* sy2 = (float*)(dyn + SM_Y2);
    float* sx2 = (float*)(dyn + SM_X2);
    float* sa  = (float*)(dyn + SM_AREA);
    unsigned int* smMask = (unsigned int*)(dyn + SM_MASK);   // [row*32 + word]
    unsigned int* sra    = (unsigned int*)(dyn + SM_RANY);

    __shared__ int sPiv;
    __shared__ int sCnt;
    __shared__ unsigned int skeep[32];
    __shared__ unsigned int warpTot[32];
    __shared__ unsigned int warpOff[32];
    __shared__ unsigned int sTotal;

    int b = blockIdx.x, tid = threadIdx.x;
    int w = tid >> 5, lane = tid & 31;

    int c = g_c1[b]; if (c > CAP1) c = CAP1;

    // ---- guarded fallback (never taken for this distribution) ----
    if (g_c1[b] < TOPK || g_c1[b] > CAP1) {
        for (int i = tid; i < 4096; i += 1024) hist[i] = 0u;
        if (tid == 0) sCnt = 0;
        __syncthreads();
        const float* sc = scores + (size_t)b * NC;
        for (int i = tid; i < NC; i += 1024) {
            float s = sc[i];
            if (s > SCORE_T) {
                int bk = (int)(s * 4096.0f); if (bk > 4095) bk = 4095;
                atomicAdd(&hist[bk], 1u);
            }
        }
        __syncthreads();
        if (tid == 0) {
            unsigned acc = 0; int piv = 0;
            for (int k = 4095; k >= 0; k--) { acc += hist[k]; if (acc >= TOPK) { piv = k; break; } }
            sPiv = piv;
        }
        __syncthreads();
        int piv = sPiv;
        for (int i = tid; i < NC; i += 1024) {
            float s = sc[i];
            if (s > SCORE_T) {
                int bk = (int)(s * 4096.0f); if (bk > 4095) bk = 4095;
                if (bk >= piv) {
                    int pos = atomicAdd(&sCnt, 1);
                    if (pos < CAP1) {
                        unsigned sb = __float_as_uint(s);
                        g_cand1[b][pos] = ((unsigned long long)sb << 32) |
                                          (unsigned long long)(0xFFFFFFFFu - (unsigned)i);
                    }
                }
            }
        }
        __syncthreads();
        c = sCnt; if (c > CAP1) c = CAP1;
    }

    // ---- fine histogram -> pivot -> compact to <= CAP ----
    for (int i = tid; i < 4096; i += 1024) hist[i] = 0u;
    for (int i = tid; i < CAP;  i += 1024) smKeys[i] = 0ull;
    if (tid == 0) sCnt = 0;
    __syncthreads();

    for (int i = tid; i < c; i += 1024) {
        float s = __uint_as_float((unsigned)(g_cand1[b][i] >> 32));
        atomicAdd(&hist[fine_bucket(s)], 1u);
    }
    __syncthreads();

    unsigned ssum = 0;
#pragma unroll
    for (int j = 0; j < 4; j++) ssum += hist[tid * 4 + j];
    chunk[tid] = ssum;
    __syncthreads();

    if (tid == 0) {
        int target = c < TOPK ? c : TOPK;
        int piv = 4096;
        if (target > 0) {
            unsigned acc = 0; bool found = false;
            piv = 0;
            for (int ch = 1023; ch >= 0 && !found; ch--) {
                if (acc + chunk[ch] >= (unsigned)target) {
                    unsigned a2 = acc;
                    for (int k2 = ch * 4 + 3; k2 >= ch * 4; k2--) {
                        a2 += hist[k2];
                        if (a2 >= (unsigned)target) { piv = k2; found = true; break; }
                    }
                } else acc += chunk[ch];
            }
        }
        sPiv = piv;
    }
    __syncthreads();

    int piv = sPiv;
    for (int i = tid; i < c; i += 1024) {
        unsigned long long key = g_cand1[b][i];
        float s = __uint_as_float((unsigned)(key >> 32));
        if (fine_bucket(s) >= piv) {
            int pos = atomicAdd(&sCnt, 1);
            if (pos < CAP) smKeys[pos] = key;
        }
    }
    __syncthreads();

    // ---- hybrid bitonic sort, descending, CAP = 2048 ----
    {
        ulonglong2* sm2 = (ulonglong2*)smKeys;
        ulonglong2 vv = sm2[tid];
        unsigned long long v0 = vv.x, v1 = vv.y;
        for (int k = 2; k <= 64; k <<= 1)
            reg_phase(v0, v1, tid, k, (k >> 1) > 32 ? 32 : (k >> 1));
        sm2[tid].x = v0; sm2[tid].y = v1;
        __syncthreads();
        for (int k = 128; k <= CAP; k <<= 1) {
            for (int j = k >> 1; j >= 64; j >>= 1) {
                for (int i = tid; i < CAP; i += 1024) {
                    int p = i ^ j;
                    if (p > i) {
                        unsigned long long A = smKeys[i], Bv = smKeys[p];
                        bool desc = ((i & k) == 0);
                        if (desc ? (A < Bv) : (A > Bv)) { smKeys[i] = Bv; smKeys[p] = A; }
                    }
                }
                __syncthreads();
            }
            vv = sm2[tid]; v0 = vv.x; v1 = vv.y;
            reg_phase(v0, v1, tid, k, 32);
            sm2[tid].x = v0; sm2[tid].y = v1;
            __syncthreads();
        }
    }

    // ---- gather: thread t owns item t; boxes stay in registers -------------
    float myScore, bc0, bc1, bc2, bc3;
    int   myCls;
    {
        unsigned long long key = smKeys[tid];
        float s = __uint_as_float((unsigned)(key >> 32));
        unsigned flat = 0xFFFFFFFFu - (unsigned)(key & 0xFFFFFFFFull);
        if (key == 0ull) { s = 0.0f; flat = 0u; }
        int bx = (int)(flat / NCLS), cl = (int)(flat % NCLS);
        const float* bp = boxes + ((size_t)b * NBOX + bx) * 4;
        bc0 = bp[0]; bc1 = bp[1]; bc2 = bp[2]; bc3 = bp[3];
        float off = (float)cl * 4096.0f;
        float o0 = bc0 + off, o1 = bc1 + off, o2 = bc2 + off, o3 = bc3 + off;
        float area = ((o3 - o1) + 1.0f) * ((o2 - o0) + 1.0f);
        myScore = s; myCls = cl;
        sy1[tid] = o0; sx1[tid] = o1; sy2[tid] = o2; sx2[tid] = o3; sa[tid] = area;
    }
    if (tid < 32) sra[tid] = 0u;
    __syncthreads();

    // ---- triangular suppression mask into smem -----------------------------
    // warp w handles rows r = w + 32*rr  (balances the triangle)
    for (int rr = 0; rr < 32; rr++) {
        int r = w + 32 * rr;
        float ry1 = sy1[r], rx1 = sx1[r], ry2 = sy2[r], rx2 = sx2[r], ra = sa[r];
        unsigned any = 0u;
        for (int cw = r >> 5; cw < 32; cw++) {
            int col = cw * 32 + lane;
            float yy1 = fmaxf(ry1, sy1[col]);
            float xx1 = fmaxf(rx1, sx1[col]);
            float yy2 = fminf(ry2, sy2[col]);
            float xx2 = fminf(rx2, sx2[col]);
            float wd = fmaxf(0.0f, (xx2 - xx1) + 1.0f);
            float ht = fmaxf(0.0f, (yy2 - yy1) + 1.0f);
            float inter = wd * ht;
            float uni = (ra + sa[col]) - inter;
            bool bit = (inter > IOU_T * uni) && (col > r);
            unsigned m = __ballot_sync(0xffffffffu, bit);
            if (lane == 0) smMask[r * 32 + cw] = m;
            any |= m;
        }
        if (lane == 0 && any) atomicOr(&sra[r >> 5], 1u << (r & 31));
    }

    // keep-init ballot
    {
        bool k0 = myScore > SCORE_T;
        unsigned bal = __ballot_sync(0xffffffffu, k0);
        if (lane == 0) skeep[w] = bal;
    }
    __syncthreads();

    // ---- serial greedy scan (warp 0, mask rows from smem) ------------------
    if (w == 0) {
        unsigned kw  = skeep[lane];
        unsigned raw = sra[lane];
        for (int g = 0; g < 32; g++) {
            unsigned curk  = __shfl_sync(0xffffffffu, kw, g);
            unsigned curra = __shfl_sync(0xffffffffu, raw, g);
            unsigned act = curk & curra;
            while (act) {
                int bit = __ffs(act) - 1;
                int i = g * 32 + bit;
                unsigned m = (lane >= g) ? smMask[i * 32 + lane] : 0u;
                kw &= ~m;
                unsigned mg = __shfl_sync(0xffffffffu, m, g);
                curk &= ~mg;
                act &= ~((2u << bit) - 1u);
                act &= curk;
            }
        }
        skeep[lane] = kw;
    }
    __syncthreads();

    // ---- stable partition + outputs ----------------------------------------
    unsigned kwword = skeep[w];
    bool keep = (kwword >> lane) & 1u;
    if (lane == 0) warpTot[w] = __popc(kwword);
    __syncthreads();
    if (tid == 0) {
        unsigned acc = 0;
        for (int i = 0; i < 32; i++) { warpOff[i] = acc; acc += warpTot[i]; }
        sTotal = acc;
    }
    __syncthreads();

    unsigned keptBefore = warpOff[w] + __popc(kwword & ((1u << lane) - 1u));
    unsigned total = sTotal;
    unsigned pos = keep ? keptBefore : (total + ((unsigned)tid - keptBefore));

    const int OFF_SCORES = BATCH * MAXDET * 4;
    const int OFF_LABELS = OFF_SCORES + BATCH * MAXDET;
    const int OFF_NVALID = OFF_LABELS + BATCH * MAXDET;

    if (pos < MAXDET) {
        float* ob = out + ((size_t)b * MAXDET + pos) * 4;
        ob[0] = bc0; ob[1] = bc1; ob[2] = bc2; ob[3] = bc3;
        out[OFF_SCORES + b * MAXDET + (int)pos] = keep ? myScore : 0.0f;
        out[OFF_LABELS + b * MAXDET + (int)pos] = (float)myCls;
    }
    if (tid == 0) {
        unsigned nv = total; if (nv > MAXDET) nv = MAXDET;
        out[OFF_NVALID + b] = (float)nv;
        g_c1[b] = 0;   // reset for next graph replay
    }
}

// ---------------- launch -----------------------------------------------------
extern "C" void kernel_launch(void* const* d_in, const int* in_sizes, int n_in,
                              void* d_out, int out_size) {
    (void)n_in; (void)out_size;
    const float* boxes;
    const float* scores;
    if (in_sizes[0] == BATCH * NBOX * 4) {
        boxes  = (const float*)d_in[0];
        scores = (const float*)d_in[1];
    } else {
        boxes  = (const float*)d_in[1];
        scores = (const float*)d_in[0];
    }

    cudaFuncSetAttribute(k_fused, cudaFuncAttributeMaxDynamicSharedMemorySize, SM_TOTAL);

    k_scan<<<SCAN_BLOCKS, 256>>>(scores);
    k_fused<<<BATCH, 1024, SM_TOTAL>>>(boxes, scores, (float*)d_out);
}

// round 11
// speedup vs baseline: 2.2045x; 2.2045x over previous
#include <cuda_runtime.h>
#include <stdint.h>

#define BATCH   32
#define NBOX    8400
#define NCLS    80
#define NC      (NBOX*NCLS)       // 672000
#define TOPK    1024
#define CAP     2048
#define CAP1    8192
#define MAXDET  300
#define SCORE_T 0.001f
#define IOU_T   0.7f
#define T0      0.995f
#define V4_PER_BATCH (NC/4)             // 168000
#define TOTAL_V4 (BATCH*V4_PER_BATCH)   // 5376000
#define SCAN_BLOCKS (TOTAL_V4/2048)     // 2625 (256 thr * 8 unroll)

// ---- dynamic smem layout (bytes) for k_fused -------------------------------
#define SM_KEYS    0                      // 2048 * 8  = 16384
#define SM_HIST    16384                  // 4096 * 4  = 16384
#define SM_CHUNK   32768                  // 1024 * 4  = 4096
#define SM_Y1      36864                  // 1024 * 4
#define SM_X1      40960
#define SM_Y2      45056
#define SM_X2      49152
#define SM_AREA    53248
#define SM_MASK    57344                  // 1024*32*4 = 131072
#define SM_RANY    188416                 // 32 * 4    = 128
#define SM_CLSCNT  188544                 // 80 * 4
#define SM_CLSOFF  188864                 // 80 * 4
#define SM_CLSFILL 189184                 // 80 * 4
#define SM_CLSLIST 189504                 // 1024 * 2
#define SM_TOTAL   191552

// ---------------- device scratch (static) -----------------------------------
__device__ int                g_c1[BATCH];            // reset by k_fused each run
__device__ unsigned long long g_cand1[BATCH][CAP1];

// ---------------- K1: single bandwidth pass, collect s > T0 -----------------
__global__ void __launch_bounds__(256) k_scan(const float* __restrict__ scores) {
    int tid  = threadIdx.x;
    int lane = tid & 31;
    size_t blockBase = (size_t)blockIdx.x * 2048;   // float4 units
    const float4* __restrict__ p = (const float4*)scores;

    float4 v[8];
#pragma unroll
    for (int k = 0; k < 8; k++)
        v[k] = p[blockBase + (size_t)k * 256 + tid];

    int b0 = (int)(blockBase / V4_PER_BATCH);
    int bL = (int)((blockBase + 2047) / V4_PER_BATCH);
    bool uniformB = (b0 == bL);

    int cnt = 0;
#pragma unroll
    for (int k = 0; k < 8; k++) {
        float a[4] = {v[k].x, v[k].y, v[k].z, v[k].w};
#pragma unroll
        for (int c = 0; c < 4; c++) cnt += (a[c] > T0) ? 1 : 0;
    }

    if (uniformB) {
        int incl = cnt;
#pragma unroll
        for (int o = 1; o < 32; o <<= 1) {
            int n = __shfl_up_sync(0xffffffffu, incl, o);
            if (lane >= o) incl += n;
        }
        int excl  = incl - cnt;
        int total = __shfl_sync(0xffffffffu, incl, 31);
        int base  = 0;
        if (total > 0) {
            if (lane == 0) base = atomicAdd(&g_c1[b0], total);
            base = __shfl_sync(0xffffffffu, base, 0);
        }
        if (cnt > 0) {
            int w = base + excl;
            size_t batchBase4 = (size_t)b0 * V4_PER_BATCH;
#pragma unroll
            for (int k = 0; k < 8; k++) {
                float a[4] = {v[k].x, v[k].y, v[k].z, v[k].w};
                size_t idx4 = blockBase + (size_t)k * 256 + tid;
#pragma unroll
                for (int c = 0; c < 4; c++) {
                    if (a[c] > T0) {
                        unsigned flat = (unsigned)((idx4 - batchBase4) * 4 + c);
                        unsigned sb = __float_as_uint(a[c]);
                        if (w < CAP1)
                            g_cand1[b0][w] = ((unsigned long long)sb << 32) |
                                             (unsigned long long)(0xFFFFFFFFu - flat);
                        w++;
                    }
                }
            }
        }
    } else {
#pragma unroll
        for (int k = 0; k < 8; k++) {
            float a[4] = {v[k].x, v[k].y, v[k].z, v[k].w};
            size_t idx4 = blockBase + (size_t)k * 256 + tid;
            int be = (int)(idx4 / V4_PER_BATCH);
#pragma unroll
            for (int c = 0; c < 4; c++) {
                if (a[c] > T0) {
                    unsigned flat = (unsigned)((idx4 - (size_t)be * V4_PER_BATCH) * 4 + c);
                    unsigned sb = __float_as_uint(a[c]);
                    int pos = atomicAdd(&g_c1[be], 1);
                    if (pos < CAP1)
                        g_cand1[be][pos] = ((unsigned long long)sb << 32) |
                                           (unsigned long long)(0xFFFFFFFFu - flat);
                }
            }
        }
    }
}

// ---------------- hybrid bitonic helpers ------------------------------------
__device__ __forceinline__ unsigned long long shfl_xor64(unsigned long long v, int lx) {
    return __shfl_xor_sync(0xffffffffu, v, lx);
}

__device__ __forceinline__ void reg_phase(unsigned long long& v0, unsigned long long& v1,
                                          int t, int k, int jstart) {
    bool desc = ((t & (k >> 1)) == 0);
    for (int j = jstart; j >= 2; j >>= 1) {
        int lx = j >> 1;
        bool low = ((t & lx) == 0);
        bool takeMax = (low == desc);
        unsigned long long o0 = shfl_xor64(v0, lx);
        unsigned long long o1 = shfl_xor64(v1, lx);
        v0 = takeMax ? (v0 > o0 ? v0 : o0) : (v0 < o0 ? v0 : o0);
        v1 = takeMax ? (v1 > o1 ? v1 : o1) : (v1 < o1 ? v1 : o1);
    }
    if (desc ? (v0 < v1) : (v0 > v1)) {
        unsigned long long tmp = v0; v0 = v1; v1 = tmp;
    }
}

__device__ __forceinline__ int fine_bucket(float s) {
    int bk = (int)((s - 0.9f) * 40960.0f);
    if (bk < 0) bk = 0; if (bk > 4095) bk = 4095;
    return bk;
}

// ---------------- K2: fused select + sparse class-bucketed NMS + output -----
__global__ void __launch_bounds__(1024) k_fused(const float* __restrict__ boxes,
                                                const float* __restrict__ scores,
                                                float* __restrict__ out) {
    extern __shared__ char dyn[];
    unsigned long long* smKeys = (unsigned long long*)(dyn + SM_KEYS);
    unsigned int* hist  = (unsigned int*)(dyn + SM_HIST);
    unsigned int* chunk = (unsigned int*)(dyn + SM_CHUNK);
    float* sy1 = (float*)(dyn + SM_Y1);
    float* sx1 = (float*)(dyn + SM_X1);
    float* sy2 = (float*)(dyn + SM_Y2);
    float* sx2 = (float*)(dyn + SM_X2);
    float* sa  = (float*)(dyn + SM_AREA);
    unsigned int* smMask = (unsigned int*)(dyn + SM_MASK);   // [row*32 + word]
    unsigned int* sra    = (unsigned int*)(dyn + SM_RANY);
    int* clsCnt  = (int*)(dyn + SM_CLSCNT);
    int* clsOff  = (int*)(dyn + SM_CLSOFF);
    int* clsFill = (int*)(dyn + SM_CLSFILL);
    unsigned short* clsList = (unsigned short*)(dyn + SM_CLSLIST);

    __shared__ int sPiv;
    __shared__ int sCnt;
    __shared__ unsigned int skeep[32];
    __shared__ unsigned int warpTot[32];
    __shared__ unsigned int warpOff[32];
    __shared__ unsigned int sTotal;

    int b = blockIdx.x, tid = threadIdx.x;
    int w = tid >> 5, lane = tid & 31;

    // zero sparse-mask scaffolding up front (consumed much later)
    for (int i = tid; i < TOPK * 32; i += 1024) smMask[i] = 0u;
    if (tid < 32) sra[tid] = 0u;
    if (tid < NCLS) { clsCnt[tid] = 0; clsFill[tid] = 0; }

    int c = g_c1[b]; if (c > CAP1) c = CAP1;

    // ---- guarded fallback (never taken for this distribution) ----
    if (g_c1[b] < TOPK || g_c1[b] > CAP1) {
        for (int i = tid; i < 4096; i += 1024) hist[i] = 0u;
        if (tid == 0) sCnt = 0;
        __syncthreads();
        const float* sc = scores + (size_t)b * NC;
        for (int i = tid; i < NC; i += 1024) {
            float s = sc[i];
            if (s > SCORE_T) {
                int bk = (int)(s * 4096.0f); if (bk > 4095) bk = 4095;
                atomicAdd(&hist[bk], 1u);
            }
        }
        __syncthreads();
        if (tid == 0) {
            unsigned acc = 0; int piv = 0;
            for (int k = 4095; k >= 0; k--) { acc += hist[k]; if (acc >= TOPK) { piv = k; break; } }
            sPiv = piv;
        }
        __syncthreads();
        int piv = sPiv;
        for (int i = tid; i < NC; i += 1024) {
            float s = sc[i];
            if (s > SCORE_T) {
                int bk = (int)(s * 4096.0f); if (bk > 4095) bk = 4095;
                if (bk >= piv) {
                    int pos = atomicAdd(&sCnt, 1);
                    if (pos < CAP1) {
                        unsigned sb = __float_as_uint(s);
                        g_cand1[b][pos] = ((unsigned long long)sb << 32) |
                                          (unsigned long long)(0xFFFFFFFFu - (unsigned)i);
                    }
                }
            }
        }
        __syncthreads();
        c = sCnt; if (c > CAP1) c = CAP1;
    }

    // ---- fine histogram -> pivot -> compact to <= CAP ----
    for (int i = tid; i < 4096; i += 1024) hist[i] = 0u;
    for (int i = tid; i < CAP;  i += 1024) smKeys[i] = 0ull;
    if (tid == 0) sCnt = 0;
    __syncthreads();

    for (int i = tid; i < c; i += 1024) {
        float s = __uint_as_float((unsigned)(g_cand1[b][i] >> 32));
        atomicAdd(&hist[fine_bucket(s)], 1u);
    }
    __syncthreads();

    unsigned ssum = 0;
#pragma unroll
    for (int j = 0; j < 4; j++) ssum += hist[tid * 4 + j];
    chunk[tid] = ssum;
    __syncthreads();

    if (tid == 0) {
        int target = c < TOPK ? c : TOPK;
        int piv = 4096;
        if (target > 0) {
            unsigned acc = 0; bool found = false;
            piv = 0;
            for (int ch = 1023; ch >= 0 && !found; ch--) {
                if (acc + chunk[ch] >= (unsigned)target) {
                    unsigned a2 = acc;
                    for (int k2 = ch * 4 + 3; k2 >= ch * 4; k2--) {
                        a2 += hist[k2];
                        if (a2 >= (unsigned)target) { piv = k2; found = true; break; }
                    }
                } else acc += chunk[ch];
            }
        }
        sPiv = piv;
    }
    __syncthreads();

    int piv = sPiv;
    for (int i = tid; i < c; i += 1024) {
        unsigned long long key = g_cand1[b][i];
        float s = __uint_as_float((unsigned)(key >> 32));
        if (fine_bucket(s) >= piv) {
            int pos = atomicAdd(&sCnt, 1);
            if (pos < CAP) smKeys[pos] = key;
        }
    }
    __syncthreads();

    // ---- hybrid bitonic sort, descending, CAP = 2048 ----
    {
        ulonglong2* sm2 = (ulonglong2*)smKeys;
        ulonglong2 vv = sm2[tid];
        unsigned long long v0 = vv.x, v1 = vv.y;
        for (int k = 2; k <= 64; k <<= 1)
            reg_phase(v0, v1, tid, k, (k >> 1) > 32 ? 32 : (k >> 1));
        sm2[tid].x = v0; sm2[tid].y = v1;
        __syncthreads();
        for (int k = 128; k <= CAP; k <<= 1) {
            for (int j = k >> 1; j >= 64; j >>= 1) {
                for (int i = tid; i < CAP; i += 1024) {
                    int p = i ^ j;
                    if (p > i) {
                        unsigned long long A = smKeys[i], Bv = smKeys[p];
                        bool desc = ((i & k) == 0);
                        if (desc ? (A < Bv) : (A > Bv)) { smKeys[i] = Bv; smKeys[p] = A; }
                    }
                }
                __syncthreads();
            }
            vv = sm2[tid]; v0 = vv.x; v1 = vv.y;
            reg_phase(v0, v1, tid, k, 32);
            sm2[tid].x = v0; sm2[tid].y = v1;
            __syncthreads();
        }
    }

    // ---- gather: thread t owns item t; coords in registers + smem ---------
    float myScore, bc0, bc1, bc2, bc3;
    float mo0, mo1, mo2, mo3, mArea;
    int   myCls;
    {
        unsigned long long key = smKeys[tid];
        float s = __uint_as_float((unsigned)(key >> 32));
        unsigned flat = 0xFFFFFFFFu - (unsigned)(key & 0xFFFFFFFFull);
        if (key == 0ull) { s = 0.0f; flat = 0u; }
        int bx = (int)(flat / NCLS), cl = (int)(flat % NCLS);
        const float* bp = boxes + ((size_t)b * NBOX + bx) * 4;
        bc0 = bp[0]; bc1 = bp[1]; bc2 = bp[2]; bc3 = bp[3];
        float off = (float)cl * 4096.0f;
        mo0 = bc0 + off; mo1 = bc1 + off; mo2 = bc2 + off; mo3 = bc3 + off;
        mArea = ((mo3 - mo1) + 1.0f) * ((mo2 - mo0) + 1.0f);
        myScore = s; myCls = cl;
        sy1[tid] = mo0; sx1[tid] = mo1; sy2[tid] = mo2; sx2[tid] = mo3; sa[tid] = mArea;
    }
    __syncthreads();

    // ---- class bucketing (cross-class IoU is exactly 0 by construction) ----
    atomicAdd(&clsCnt[myCls], 1);
    __syncthreads();
    if (tid == 0) {
        int acc = 0;
        for (int cc = 0; cc < NCLS; cc++) { clsOff[cc] = acc; acc += clsCnt[cc]; }
    }
    __syncthreads();
    {
        int pos = atomicAdd(&clsFill[myCls], 1);
        clsList[clsOff[myCls] + pos] = (unsigned short)tid;
    }
    __syncthreads();

    // ---- sparse suppression: only same-class, later-index pairs ------------
    {
        int base = clsOff[myCls];
        int n    = clsCnt[myCls];
        bool any = false;
        for (int ii = 0; ii < n; ii++) {
            int m = clsList[base + ii];
            if (m > tid) {
                float yy1 = fmaxf(mo0, sy1[m]);
                float xx1 = fmaxf(mo1, sx1[m]);
                float yy2 = fminf(mo2, sy2[m]);
                float xx2 = fminf(mo3, sx2[m]);
                float wd = fmaxf(0.0f, (xx2 - xx1) + 1.0f);
                float ht = fmaxf(0.0f, (yy2 - yy1) + 1.0f);
                float inter = wd * ht;
                float uni = (mArea + sa[m]) - inter;
                if (inter > IOU_T * uni) {
                    atomicOr(&smMask[tid * 32 + (m >> 5)], 1u << (m & 31));
                    any = true;
                }
            }
        }
        if (any) atomicOr(&sra[tid >> 5], 1u << (tid & 31));
    }

    // keep-init ballot
    {
        bool k0 = myScore > SCORE_T;
        unsigned bal = __ballot_sync(0xffffffffu, k0);
        if (lane == 0) skeep[w] = bal;
    }
    __syncthreads();

    // ---- serial greedy scan (warp 0, mask rows from smem) ------------------
    if (w == 0) {
        unsigned kw  = skeep[lane];
        unsigned raw = sra[lane];
        for (int g = 0; g < 32; g++) {
            unsigned curk  = __shfl_sync(0xffffffffu, kw, g);
            unsigned curra = __shfl_sync(0xffffffffu, raw, g);
            unsigned act = curk & curra;
            while (act) {
                int bit = __ffs(act) - 1;
                int i = g * 32 + bit;
                unsigned m = smMask[i * 32 + lane];
                kw &= ~m;
                unsigned mg = __shfl_sync(0xffffffffu, m, g);
                curk &= ~mg;
                act &= ~((2u << bit) - 1u);
                act &= curk;
            }
        }
        skeep[lane] = kw;
    }
    __syncthreads();

    // ---- stable partition + outputs ----------------------------------------
    unsigned kwword = skeep[w];
    bool keep = (kwword >> lane) & 1u;
    if (lane == 0) warpTot[w] = __popc(kwword);
    __syncthreads();
    if (tid == 0) {
        unsigned acc = 0;
        for (int i = 0; i < 32; i++) { warpOff[i] = acc; acc += warpTot[i]; }
        sTotal = acc;
    }
    __syncthreads();

    unsigned keptBefore = warpOff[w] + __popc(kwword & ((1u << lane) - 1u));
    unsigned total = sTotal;
    unsigned pos = keep ? keptBefore : (total + ((unsigned)tid - keptBefore));

    const int OFF_SCORES = BATCH * MAXDET * 4;
    const int OFF_LABELS = OFF_SCORES + BATCH * MAXDET;
    const int OFF_NVALID = OFF_LABELS + BATCH * MAXDET;

    if (pos < MAXDET) {
        float* ob = out + ((size_t)b * MAXDET + pos) * 4;
        ob[0] = bc0; ob[1] = bc1; ob[2] = bc2; ob[3] = bc3;
        out[OFF_SCORES + b * MAXDET + (int)pos] = keep ? myScore : 0.0f;
        out[OFF_LABELS + b * MAXDET + (int)pos] = (float)myCls;
    }
    if (tid == 0) {
        unsigned nv = total; if (nv > MAXDET) nv = MAXDET;
        out[OFF_NVALID + b] = (float)nv;
        g_c1[b] = 0;   // reset for next graph replay
    }
}

// ---------------- launch -----------------------------------------------------
extern "C" void kernel_launch(void* const* d_in, const int* in_sizes, int n_in,
                              void* d_out, int out_size) {
    (void)n_in; (void)out_size;
    const float* boxes;
    const float* scores;
    if (in_sizes[0] == BATCH * NBOX * 4) {
        boxes  = (const float*)d_in[0];
        scores = (const float*)d_in[1];
    } else {
        boxes  = (const float*)d_in[1];
        scores = (const float*)d_in[0];
    }

    cudaFuncSetAttribute(k_fused, cudaFuncAttributeMaxDynamicSharedMemorySize, SM_TOTAL);

    k_scan<<<SCAN_BLOCKS, 256>>>(scores);
    k_fused<<<BATCH, 1024, SM_TOTAL>>>(boxes, scores, (float*)d_out);
}

// round 12
// speedup vs baseline: 2.6706x; 1.2114x over previous
#include <cuda_runtime.h>
#include <stdint.h>

#define BATCH   32
#define NBOX    8400
#define NCLS    80
#define NC      (NBOX*NCLS)       // 672000
#define TOPK    1024
#define CAP     2048
#define CAP1    8192
#define MAXDET  300
#define SCORE_T 0.001f
#define IOU_T   0.7f
#define T0      0.995f
#define V4_PER_BATCH (NC/4)             // 168000
#define TOTAL_V4 (BATCH*V4_PER_BATCH)   // 5376000
#define SCAN_BLOCKS (TOTAL_V4/2048)     // 2625 (chunks of 2048 float4)
#define GRID    148                     // <= SM count: all CTAs resident (safe spin barrier)

// ---- dynamic smem layout (bytes), all 8-aligned ----------------------------
#define SM_SLOT    0                      // 2048 * 8 = 16384  (bucket-grouped keys)
#define SM_SORT    16384                  // 1024 * 8 = 8192   (exact sorted top-1024)
#define SM_CNT     24576                  // 2048 * 4 = 8192   (fine hist counts)
#define SM_START   32768                  // 2048 * 4 = 8192   (desc exclusive prefix)
#define SM_FILL    40960                  // 2048 * 4 = 8192
#define SM_Y1      49152                  // 1024 * 4
#define SM_X1      53248
#define SM_Y2      57344
#define SM_X2      61440
#define SM_AREA    65536                  // ends 69632
#define SM_MASK    69632                  // 1024*32*4 = 131072 -> 200704
#define SM_RANY    200704                 // 128
#define SM_CLSCNT  200832                 // 320
#define SM_CLSOFF  201152                 // 320
#define SM_CLSFILL 201472                 // 320
#define SM_CLSLIST 201792                 // 2048
#define SM_WSCAN   203840                 // 128
#define SM_TOTAL   203968

// ---------------- device scratch (static) -----------------------------------
__device__ int                g_c1[BATCH];            // reset at end of each run
__device__ unsigned long long g_cand1[BATCH][CAP1];
__device__ unsigned           g_arrive;               // self-resetting
__device__ volatile unsigned  g_gen;                  // monotone generation

// ---------------- phase 1 helper: scan one 2048-float4 chunk ----------------
__device__ __forceinline__ void scan_block(const float4* __restrict__ p, int bb,
                                           int tid, int lane) {
    size_t blockBase = (size_t)bb * 2048;

    float4 v[8];
#pragma unroll
    for (int k = 0; k < 8; k++)
        v[k] = p[blockBase + (size_t)k * 256 + (tid & 255)];

    int b0 = (int)(blockBase / V4_PER_BATCH);
    int bL = (int)((blockBase + 2047) / V4_PER_BATCH);
    bool uniformB = (b0 == bL);

    int cnt = 0;
#pragma unroll
    for (int k = 0; k < 8; k++) {
        float a[4] = {v[k].x, v[k].y, v[k].z, v[k].w};
#pragma unroll
        for (int c = 0; c < 4; c++) cnt += (a[c] > T0) ? 1 : 0;
    }

    if (uniformB) {
        int incl = cnt;
#pragma unroll
        for (int o = 1; o < 32; o <<= 1) {
            int n = __shfl_up_sync(0xffffffffu, incl, o);
            if (lane >= o) incl += n;
        }
        int excl  = incl - cnt;
        int total = __shfl_sync(0xffffffffu, incl, 31);
        int base  = 0;
        if (total > 0) {
            if (lane == 0) base = atomicAdd(&g_c1[b0], total);
            base = __shfl_sync(0xffffffffu, base, 0);
        }
        if (cnt > 0) {
            int w = base + excl;
            size_t batchBase4 = (size_t)b0 * V4_PER_BATCH;
#pragma unroll
            for (int k = 0; k < 8; k++) {
                float a[4] = {v[k].x, v[k].y, v[k].z, v[k].w};
                size_t idx4 = blockBase + (size_t)k * 256 + (tid & 255);
#pragma unroll
                for (int c = 0; c < 4; c++) {
                    if (a[c] > T0) {
                        unsigned flat = (unsigned)((idx4 - batchBase4) * 4 + c);
                        unsigned sb = __float_as_uint(a[c]);
                        if (w < CAP1)
                            g_cand1[b0][w] = ((unsigned long long)sb << 32) |
                                             (unsigned long long)(0xFFFFFFFFu - flat);
                        w++;
                    }
                }
            }
        }
    } else {
#pragma unroll
        for (int k = 0; k < 8; k++) {
            float a[4] = {v[k].x, v[k].y, v[k].z, v[k].w};
            size_t idx4 = blockBase + (size_t)k * 256 + (tid & 255);
            int be = (int)(idx4 / V4_PER_BATCH);
#pragma unroll
            for (int c = 0; c < 4; c++) {
                if (a[c] > T0) {
                    unsigned flat = (unsigned)((idx4 - (size_t)be * V4_PER_BATCH) * 4 + c);
                    unsigned sb = __float_as_uint(a[c]);
                    int pos = atomicAdd(&g_c1[be], 1);
                    if (pos < CAP1)
                        g_cand1[be][pos] = ((unsigned long long)sb << 32) |
                                           (unsigned long long)(0xFFFFFFFFu - flat);
                }
            }
        }
    }
}

__device__ __forceinline__ int fine_bucket(float s) {
    int bk = (int)((s - 0.95f) * 40960.0f);     // [0.95, 1.0] -> [0, 2047]
    if (bk < 0) bk = 0; if (bk > 2047) bk = 2047;
    return bk;
}

// ---------------- single persistent kernel ----------------------------------
__global__ void __launch_bounds__(1024) k_all(const float* __restrict__ boxes,
                                              const float* __restrict__ scores,
                                              float* __restrict__ out) {
    extern __shared__ char dyn[];
    unsigned long long* slotK = (unsigned long long*)(dyn + SM_SLOT);
    unsigned long long* sortK = (unsigned long long*)(dyn + SM_SORT);
    unsigned int* cntA   = (unsigned int*)(dyn + SM_CNT);
    unsigned int* startA = (unsigned int*)(dyn + SM_START);
    unsigned int* fillA  = (unsigned int*)(dyn + SM_FILL);
    float* sy1 = (float*)(dyn + SM_Y1);
    float* sx1 = (float*)(dyn + SM_X1);
    float* sy2 = (float*)(dyn + SM_Y2);
    float* sx2 = (float*)(dyn + SM_X2);
    float* sa  = (float*)(dyn + SM_AREA);
    unsigned int* smMask = (unsigned int*)(dyn + SM_MASK);
    unsigned int* sra    = (unsigned int*)(dyn + SM_RANY);
    int* clsCnt  = (int*)(dyn + SM_CLSCNT);
    int* clsOff  = (int*)(dyn + SM_CLSOFF);
    int* clsFill = (int*)(dyn + SM_CLSFILL);
    unsigned short* clsList = (unsigned short*)(dyn + SM_CLSLIST);
    unsigned int* wscan = (unsigned int*)(dyn + SM_WSCAN);

    __shared__ int sPiv;
    __shared__ int sCnt;
    __shared__ unsigned int skeep[32];
    __shared__ unsigned int warpTot[32];
    __shared__ unsigned int warpOff[32];
    __shared__ unsigned int sTotal;

    int tid = threadIdx.x;
    int w = tid >> 5, lane = tid & 31;

    // ================= phase 1: full-chip score scan =========================
    {
        const float4* p = (const float4*)scores;
        // 256-thread sub-blocks: warps 0-7 handle chunk 4*bb_base+sub ...
        // simpler: each CTA processes chunks bb = blockIdx.x*? -> use 4 sub-groups
        // Each 2048-float4 chunk is handled by 256 threads; CTA has 4 such groups.
        int grp = tid >> 8;                      // 0..3
        for (int bb = blockIdx.x * 4 + grp; bb < SCAN_BLOCKS; bb += GRID * 4)
            scan_block(p, bb, tid, lane);
    }

    // ================= device-wide sense-reversing barrier ===================
    __syncthreads();
    if (tid == 0) {
        __threadfence();
        unsigned gen = g_gen;
        unsigned a = atomicAdd(&g_arrive, 1u);
        if (a == (unsigned)(gridDim.x - 1)) {
            g_arrive = 0;
            __threadfence();
            atomicAdd((unsigned*)&g_gen, 1u);
        } else {
            while (g_gen == gen) __nanosleep(64);
        }
        __threadfence();
    }
    __syncthreads();

    if (blockIdx.x >= BATCH) return;
    int b = blockIdx.x;

    // ================= phase 2: select + NMS + output ========================
    int cRaw = g_c1[b];
    int c = cRaw; if (c > CAP1) c = CAP1;

    // ---- guarded fallback (never taken for this distribution) ----
    if (cRaw < TOPK || cRaw > CAP1) {
        unsigned int* hist4096 = cntA;           // cnt+start regions are contiguous
        for (int i = tid; i < 4096; i += 1024) hist4096[i] = 0u;
        if (tid == 0) sCnt = 0;
        __syncthreads();
        const float* sc = scores + (size_t)b * NC;
        for (int i = tid; i < NC; i += 1024) {
            float s = sc[i];
            if (s > SCORE_T) {
                int bk = (int)(s * 4096.0f); if (bk > 4095) bk = 4095;
                atomicAdd(&hist4096[bk], 1u);
            }
        }
        __syncthreads();
        if (tid == 0) {
            unsigned acc = 0; int piv = 0;
            for (int k = 4095; k >= 0; k--) { acc += hist4096[k]; if (acc >= TOPK) { piv = k; break; } }
            sPiv = piv;
        }
        __syncthreads();
        int piv = sPiv;
        for (int i = tid; i < NC; i += 1024) {
            float s = sc[i];
            if (s > SCORE_T) {
                int bk = (int)(s * 4096.0f); if (bk > 4095) bk = 4095;
                if (bk >= piv) {
                    int pos = atomicAdd(&sCnt, 1);
                    if (pos < CAP1) {
                        unsigned sb = __float_as_uint(s);
                        g_cand1[b][pos] = ((unsigned long long)sb << 32) |
                                          (unsigned long long)(0xFFFFFFFFu - (unsigned)i);
                    }
                }
            }
        }
        __syncthreads();
        c = sCnt; if (c > CAP1) c = CAP1;
    }

    // ---- zero scaffolding ----
    for (int i = tid; i < 2048; i += 1024) { cntA[i] = 0u; fillA[i] = 0u; }
    sortK[tid] = 0ull;
    {
        uint4* m4 = (uint4*)smMask;
        for (int i = tid; i < (TOPK * 32) / 4; i += 1024)
            m4[i] = make_uint4(0u, 0u, 0u, 0u);
    }
    if (tid < 32) sra[tid] = 0u;
    if (tid < NCLS) { clsCnt[tid] = 0; clsFill[tid] = 0; }
    __syncthreads();

    // ---- counting sort: hist -> desc prefix -> scatter -> in-bucket rank ----
    for (int i = tid; i < c; i += 1024) {
        float s = __uint_as_float((unsigned)(g_cand1[b][i] >> 32));
        atomicAdd(&cntA[fine_bucket(s)], 1u);
    }
    __syncthreads();

    {   // descending exclusive prefix: start[bk] = sum cnt over buckets > bk
        unsigned c0  = cntA[2047 - 2 * tid];
        unsigned c1v = cntA[2047 - (2 * tid + 1)];
        unsigned psum = c0 + c1v;
        unsigned incl = psum;
#pragma unroll
        for (int o = 1; o < 32; o <<= 1) {
            unsigned n = __shfl_up_sync(0xffffffffu, incl, o);
            if (lane >= o) incl += n;
        }
        if (lane == 31) wscan[w] = incl;
        __syncthreads();
        if (w == 0) {
            unsigned v = wscan[lane];
            unsigned i2 = v;
#pragma unroll
            for (int o = 1; o < 32; o <<= 1) {
                unsigned n = __shfl_up_sync(0xffffffffu, i2, o);
                if (lane >= o) i2 += n;
            }
            wscan[lane] = i2 - v;
        }
        __syncthreads();
        unsigned base = wscan[w] + (incl - psum);
        startA[2047 - 2 * tid] = base;
        startA[2047 - (2 * tid + 1)] = base + c0;
    }
    __syncthreads();

    for (int i = tid; i < c; i += 1024) {
        unsigned long long key = g_cand1[b][i];
        float s = __uint_as_float((unsigned)(key >> 32));
        int bk = fine_bucket(s);
        unsigned pos = startA[bk] + atomicAdd(&fillA[bk], 1u);
        if (pos < CAP) slotK[pos] = key;
    }
    __syncthreads();

    {
        int Nw = c < CAP ? c : CAP;      // written slots are exactly [0, Nw)
        for (int t = tid; t < Nw; t += 1024) {
            unsigned long long key = slotK[t];
            float s = __uint_as_float((unsigned)(key >> 32));
            int bk = fine_bucket(s);
            unsigned lo = startA[bk];
            unsigned hi = lo + cntA[bk]; if (hi > (unsigned)CAP) hi = CAP;
            unsigned r = lo;
            for (unsigned q = lo; q < hi; q++)
                r += (slotK[q] > key) ? 1u : 0u;
            if (r < TOPK) sortK[r] = key;
        }
    }
    __syncthreads();

    // ---- gather: thread t owns sorted item t --------------------------------
    float myScore, bc0, bc1, bc2, bc3;
    float mo0, mo1, mo2, mo3, mArea;
    int   myCls;
    {
        unsigned long long key = sortK[tid];
        float s = __uint_as_float((unsigned)(key >> 32));
        unsigned flat = 0xFFFFFFFFu - (unsigned)(key & 0xFFFFFFFFull);
        if (key == 0ull) { s = 0.0f; flat = 0u; }
        int bx = (int)(flat / NCLS), cl = (int)(flat % NCLS);
        const float4 bp = ((const float4*)boxes)[(size_t)b * NBOX + bx];
        bc0 = bp.x; bc1 = bp.y; bc2 = bp.z; bc3 = bp.w;
        float off = (float)cl * 4096.0f;
        mo0 = bc0 + off; mo1 = bc1 + off; mo2 = bc2 + off; mo3 = bc3 + off;
        mArea = ((mo3 - mo1) + 1.0f) * ((mo2 - mo0) + 1.0f);
        myScore = s; myCls = cl;
        sy1[tid] = mo0; sx1[tid] = mo1; sy2[tid] = mo2; sx2[tid] = mo3; sa[tid] = mArea;
    }
    __syncthreads();

    // ---- class bucketing (cross-class IoU is exactly 0 by construction) ----
    atomicAdd(&clsCnt[myCls], 1);
    __syncthreads();
    if (tid == 0) {
        int acc = 0;
        for (int cc = 0; cc < NCLS; cc++) { clsOff[cc] = acc; acc += clsCnt[cc]; }
    }
    __syncthreads();
    {
        int pos = atomicAdd(&clsFill[myCls], 1);
        clsList[clsOff[myCls] + pos] = (unsigned short)tid;
    }
    __syncthreads();

    // ---- sparse suppression: only same-class, later-index pairs ------------
    {
        int base = clsOff[myCls];
        int n    = clsCnt[myCls];
        bool any = false;
        for (int ii = 0; ii < n; ii++) {
            int m = clsList[base + ii];
            if (m > tid) {
                float yy1 = fmaxf(mo0, sy1[m]);
                float xx1 = fmaxf(mo1, sx1[m]);
                float yy2 = fminf(mo2, sy2[m]);
                float xx2 = fminf(mo3, sx2[m]);
                float wd = fmaxf(0.0f, (xx2 - xx1) + 1.0f);
                float ht = fmaxf(0.0f, (yy2 - yy1) + 1.0f);
                float inter = wd * ht;
                float uni = (mArea + sa[m]) - inter;
                if (inter > IOU_T * uni) {
                    atomicOr(&smMask[tid * 32 + (m >> 5)], 1u << (m & 31));
                    any = true;
                }
            }
        }
        if (any) atomicOr(&sra[tid >> 5], 1u << (tid & 31));
    }

    {
        bool k0 = myScore > SCORE_T;
        unsigned bal = __ballot_sync(0xffffffffu, k0);
        if (lane == 0) skeep[w] = bal;
    }
    __syncthreads();

    // ---- serial greedy scan (warp 0, mask rows from smem) ------------------
    if (w == 0) {
        unsigned kw  = skeep[lane];
        unsigned raw = sra[lane];
        for (int g = 0; g < 32; g++) {
            unsigned curk  = __shfl_sync(0xffffffffu, kw, g);
            unsigned curra = __shfl_sync(0xffffffffu, raw, g);
            unsigned act = curk & curra;
            while (act) {
                int bit = __ffs(act) - 1;
                int i = g * 32 + bit;
                unsigned m = smMask[i * 32 + lane];
                kw &= ~m;
                unsigned mg = __shfl_sync(0xffffffffu, m, g);
                curk &= ~mg;
                act &= ~((2u << bit) - 1u);
                act &= curk;
            }
        }
        skeep[lane] = kw;
    }
    __syncthreads();

    // ---- stable partition + outputs ----------------------------------------
    unsigned kwword = skeep[w];
    bool keep = (kwword >> lane) & 1u;
    if (lane == 0) warpTot[w] = __popc(kwword);
    __syncthreads();
    if (tid == 0) {
        unsigned acc = 0;
        for (int i = 0; i < 32; i++) { warpOff[i] = acc; acc += warpTot[i]; }
        sTotal = acc;
    }
    __syncthreads();

    unsigned keptBefore = warpOff[w] + __popc(kwword & ((1u << lane) - 1u));
    unsigned total = sTotal;
    unsigned pos = keep ? keptBefore : (total + ((unsigned)tid - keptBefore));

    const int OFF_SCORES = BATCH * MAXDET * 4;
    const int OFF_LABELS = OFF_SCORES + BATCH * MAXDET;
    const int OFF_NVALID = OFF_LABELS + BATCH * MAXDET;

    if (pos < MAXDET) {
        float* ob = out + ((size_t)b * MAXDET + pos) * 4;
        ob[0] = bc0; ob[1] = bc1; ob[2] = bc2; ob[3] = bc3;
        out[OFF_SCORES + b * MAXDET + (int)pos] = keep ? myScore : 0.0f;
        out[OFF_LABELS + b * MAXDET + (int)pos] = (float)myCls;
    }
    if (tid == 0) {
        unsigned nv = total; if (nv > MAXDET) nv = MAXDET;
        out[OFF_NVALID + b] = (float)nv;
        g_c1[b] = 0;   // reset for next graph replay
    }
}

// ---------------- launch -----------------------------------------------------
extern "C" void kernel_launch(void* const* d_in, const int* in_sizes, int n_in,
                              void* d_out, int out_size) {
    (void)n_in; (void)out_size;
    const float* boxes;
    const float* scores;
    if (in_sizes[0] == BATCH * NBOX * 4) {
        boxes  = (const float*)d_in[0];
        scores = (const float*)d_in[1];
    } else {
        boxes  = (const float*)d_in[1];
        scores = (const float*)d_in[0];
    }

    cudaFuncSetAttribute(k_all, cudaFuncAttributeMaxDynamicSharedMemorySize, SM_TOTAL);

    k_all<<<GRID, 1024, SM_TOTAL>>>(boxes, scores, (float*)d_out);
}